// round 1
// baseline (speedup 1.0000x reference)
#include <cuda_runtime.h>

#define Dm 512
#define Sq 512
#define Bz 4
#define Hh 8
#define DK 64
#define FF 2048
#define NL 6
#define TOK (Bz*Sq)        // 2048 tokens
#define NEGV (-1000000000.0f)

// ---------------- scratch (no allocations allowed) ----------------
__device__ float g_Q  [TOK*Dm];
__device__ float g_K  [TOK*Dm];
__device__ float g_V  [TOK*Dm];
__device__ float g_Sc [Bz*Hh*Sq*Sq];   // 32 MB attention scores
__device__ float g_Ctx[TOK*Dm];
__device__ float g_Tmp[TOK*Dm];
__device__ float g_Ffn[TOK*FF];
__device__ float g_Enc[TOK*Dm];
__device__ float g_Dec[TOK*Dm];

// ---------------- GEMM: C[M,N] = A[M,K] @ B[K,N], optional ReLU ----------------
// 64x64 block tile, BK=16, 16x16 threads, 4x4 micro-tile per thread.
template<bool RELU>
__global__ void gemm64(const float* __restrict__ A, const float* __restrict__ B,
                       float* __restrict__ C, int M, int N, int K) {
    __shared__ float As[16][64];   // transposed: As[k][m]
    __shared__ float Bs[16][64];
    const int tx = threadIdx.x, ty = threadIdx.y;
    const int tid = ty * 16 + tx;
    const int rowBase = blockIdx.y * 64;
    const int colBase = blockIdx.x * 64;
    float acc[4][4] = {};
    for (int k0 = 0; k0 < K; k0 += 16) {
        // A tile: 64 rows x 16 k  (float4 along K, scatter to transposed As)
        {
            int m   = tid >> 2;          // 0..63
            int kk4 = (tid & 3) * 4;     // 0,4,8,12
            float4 a = *(const float4*)&A[(size_t)(rowBase + m) * K + k0 + kk4];
            As[kk4 + 0][m] = a.x; As[kk4 + 1][m] = a.y;
            As[kk4 + 2][m] = a.z; As[kk4 + 3][m] = a.w;
        }
        // B tile: 16 k x 64 n
        {
            int kk = tid >> 4;           // 0..15
            int n4 = (tid & 15) * 4;
            *(float4*)&Bs[kk][n4] = *(const float4*)&B[(size_t)(k0 + kk) * N + colBase + n4];
        }
        __syncthreads();
        #pragma unroll
        for (int kk = 0; kk < 16; kk++) {
            float4 a4 = *(const float4*)&As[kk][ty * 4];
            float4 b4 = *(const float4*)&Bs[kk][tx * 4];
            float av[4] = {a4.x, a4.y, a4.z, a4.w};
            float bv[4] = {b4.x, b4.y, b4.z, b4.w};
            #pragma unroll
            for (int i = 0; i < 4; i++)
                #pragma unroll
                for (int j = 0; j < 4; j++)
                    acc[i][j] += av[i] * bv[j];
        }
        __syncthreads();
    }
    #pragma unroll
    for (int i = 0; i < 4; i++) {
        float4 o;
        float v0 = acc[i][0], v1 = acc[i][1], v2 = acc[i][2], v3 = acc[i][3];
        if (RELU) { v0 = fmaxf(v0, 0.f); v1 = fmaxf(v1, 0.f); v2 = fmaxf(v2, 0.f); v3 = fmaxf(v3, 0.f); }
        o.x = v0; o.y = v1; o.z = v2; o.w = v3;
        *(float4*)&C[(size_t)(rowBase + ty * 4 + i) * N + colBase + tx * 4] = o;
    }
}

// ---------------- scores[bh, q, k] = Q[b,q,h,:] . K[b,k,h,:] * 1/sqrt(64) ----------------
// block = 32x32 output tile for one (b,h); inner dim 64 fully in smem.
__global__ void scores_kernel(const float* __restrict__ Q, const float* __restrict__ K,
                              float* __restrict__ S) {
    const int bh = blockIdx.z;
    const int b = bh >> 3, h = bh & 7;
    __shared__ float Qs[32][64];
    __shared__ float Ks[32][65];      // padded: Ks[tx][d] stride-65 -> conflict free
    const int q0 = blockIdx.y * 32, k0 = blockIdx.x * 32;
    const int tx = threadIdx.x, ty = threadIdx.y;
    const int tid = ty * 32 + tx;
    for (int e = tid; e < 32 * 64; e += 1024) {
        int r = e >> 6, d = e & 63;
        Qs[r][d] = Q[(size_t)((b * Sq + q0 + r) * Dm) + h * DK + d];
        Ks[r][d] = K[(size_t)((b * Sq + k0 + r) * Dm) + h * DK + d];
    }
    __syncthreads();
    float acc = 0.f;
    #pragma unroll
    for (int d = 0; d < 64; d++) acc += Qs[ty][d] * Ks[tx][d];
    S[(size_t)(bh * Sq + q0 + ty) * Sq + k0 + tx] = acc * 0.125f;
}

// ---------------- row softmax over 512, optional mask (mask==0 -> -1e9) ----------------
__global__ void softmax_kernel(float* __restrict__ S, const int* __restrict__ mask) {
    const int row = blockIdx.x;        // bh*512 + q
    const int q = row & 511;
    const int bh = row >> 9;
    const int b = bh >> 3;
    float* p = S + (size_t)row * Sq;
    const int t = threadIdx.x;         // 256 threads, 2 elems each
    float v0 = p[t], v1 = p[t + 256];
    if (mask) {
        const int* mrow = mask + (size_t)(b * Sq + q) * Sq;
        if (mrow[t] == 0)       v0 = NEGV;
        if (mrow[t + 256] == 0) v1 = NEGV;
    }
    __shared__ float red[256];
    red[t] = fmaxf(v0, v1); __syncthreads();
    for (int s = 128; s > 0; s >>= 1) { if (t < s) red[t] = fmaxf(red[t], red[t + s]); __syncthreads(); }
    float m = red[0]; __syncthreads();
    float e0 = __expf(v0 - m), e1 = __expf(v1 - m);
    red[t] = e0 + e1; __syncthreads();
    for (int s = 128; s > 0; s >>= 1) { if (t < s) red[t] += red[t + s]; __syncthreads(); }
    float inv = 1.0f / red[0];
    p[t] = e0 * inv; p[t + 256] = e1 * inv;
}

// ---------------- ctx[b,q,h,:] = sum_k attn[bh,q,k] * V[b,k,h,:] ----------------
// block: 32 q-rows x 64 d-cols for one (b,h); threads (64,4), 8 q-rows per thread.
__global__ void ctx_kernel(const float* __restrict__ P, const float* __restrict__ V,
                           float* __restrict__ C) {
    const int bh = blockIdx.z, b = bh >> 3, h = bh & 7;
    const int q0 = blockIdx.x * 32;
    __shared__ float Ps[32][33];
    __shared__ float Vs[32][64];
    const int tx = threadIdx.x;   // d: 0..63
    const int ty = threadIdx.y;   // 0..3
    const int tid = ty * 64 + tx;
    float acc[8] = {};
    for (int k0 = 0; k0 < Sq; k0 += 32) {
        for (int e = tid; e < 32 * 32; e += 256) {
            int r = e >> 5, c = e & 31;
            Ps[r][c] = P[(size_t)(bh * Sq + q0 + r) * Sq + k0 + c];
        }
        for (int e = tid; e < 32 * 64; e += 256) {
            int r = e >> 6, d = e & 63;
            Vs[r][d] = V[(size_t)((b * Sq + k0 + r) * Dm) + h * DK + d];
        }
        __syncthreads();
        #pragma unroll
        for (int kk = 0; kk < 32; kk++) {
            float vv = Vs[kk][tx];
            #pragma unroll
            for (int i = 0; i < 8; i++)
                acc[i] += Ps[ty + i * 4][kk] * vv;
        }
        __syncthreads();
    }
    #pragma unroll
    for (int i = 0; i < 8; i++)
        C[(size_t)((b * Sq + q0 + ty + i * 4) * Dm) + h * DK + tx] = acc[i];
}

// ---------------- out = LayerNorm(X + R), row = 512 elems ----------------
__global__ void add_ln_kernel(const float* __restrict__ X, const float* __restrict__ R,
                              float* __restrict__ O) {
    const int row = blockIdx.x;
    const int t = threadIdx.x;   // 256 threads, 2 elems each
    const float* x = X + (size_t)row * Dm;
    const float* r = R + (size_t)row * Dm;
    float v0 = x[t] + r[t], v1 = x[t + 256] + r[t + 256];
    __shared__ float red[256];
    red[t] = v0 + v1; __syncthreads();
    for (int s = 128; s > 0; s >>= 1) { if (t < s) red[t] += red[t + s]; __syncthreads(); }
    float mean = red[0] * (1.0f / Dm); __syncthreads();
    float d0 = v0 - mean, d1 = v1 - mean;
    red[t] = d0 * d0 + d1 * d1; __syncthreads();
    for (int s = 128; s > 0; s >>= 1) { if (t < s) red[t] += red[t + s]; __syncthreads(); }
    float inv = rsqrtf(red[0] * (1.0f / Dm) + 1e-5f);
    float* o = O + (size_t)row * Dm;
    o[t] = d0 * inv; o[t + 256] = d1 * inv;
}

// ---------------- host orchestration ----------------
struct Bufs { float *Q, *K, *V, *Sc, *Ctx, *Tmp, *Ffn, *Enc, *Dec; };

static void attn_block(const float* xq, const float* xkv,
                       const float* Wq, const float* Wk, const float* Wv, const float* Wo,
                       const int* mask, float* dst, const Bufs& bf) {
    dim3 gP(Dm / 64, TOK / 64), bG(16, 16);
    gemm64<false><<<gP, bG>>>(xq,  Wq, bf.Q, TOK, Dm, Dm);
    gemm64<false><<<gP, bG>>>(xkv, Wk, bf.K, TOK, Dm, Dm);
    gemm64<false><<<gP, bG>>>(xkv, Wv, bf.V, TOK, Dm, Dm);
    scores_kernel<<<dim3(Sq / 32, Sq / 32, Bz * Hh), dim3(32, 32)>>>(bf.Q, bf.K, bf.Sc);
    softmax_kernel<<<Bz * Hh * Sq, 256>>>(bf.Sc, mask);
    ctx_kernel<<<dim3(Sq / 32, 1, Bz * Hh), dim3(64, 4)>>>(bf.Sc, bf.V, bf.Ctx);
    gemm64<false><<<gP, bG>>>(bf.Ctx, Wo, bf.Tmp, TOK, Dm, Dm);
    add_ln_kernel<<<TOK, 256>>>(bf.Tmp, xq, dst);
}

static void ffn_block(const float* x, const float* W1, const float* W2,
                      float* dst, const Bufs& bf) {
    gemm64<true ><<<dim3(FF / 64, TOK / 64), dim3(16, 16)>>>(x, W1, bf.Ffn, TOK, FF, Dm);
    gemm64<false><<<dim3(Dm / 64, TOK / 64), dim3(16, 16)>>>(bf.Ffn, W2, bf.Tmp, TOK, Dm, FF);
    add_ln_kernel<<<TOK, 256>>>(bf.Tmp, x, dst);
}

extern "C" void kernel_launch(void* const* d_in, const int* in_sizes, int n_in,
                              void* d_out, int out_size) {
    const float* enc_in  = (const float*)d_in[0];
    const float* dec_in  = (const float*)d_in[1];
    const int*   mask    = (const int*)  d_in[2];
    const float* enc_Wq  = (const float*)d_in[3];
    const float* enc_Wk  = (const float*)d_in[4];
    const float* enc_Wv  = (const float*)d_in[5];
    const float* enc_Wo  = (const float*)d_in[6];
    const float* enc_W1  = (const float*)d_in[7];
    const float* enc_W2  = (const float*)d_in[8];
    const float* sa_Wq   = (const float*)d_in[9];
    const float* sa_Wk   = (const float*)d_in[10];
    const float* sa_Wv   = (const float*)d_in[11];
    const float* sa_Wo   = (const float*)d_in[12];
    const float* ca_Wq   = (const float*)d_in[13];
    const float* ca_Wk   = (const float*)d_in[14];
    const float* ca_Wv   = (const float*)d_in[15];
    const float* ca_Wo   = (const float*)d_in[16];
    const float* dec_W1  = (const float*)d_in[17];
    const float* dec_W2  = (const float*)d_in[18];

    Bufs bf;
    cudaGetSymbolAddress((void**)&bf.Q,   g_Q);
    cudaGetSymbolAddress((void**)&bf.K,   g_K);
    cudaGetSymbolAddress((void**)&bf.V,   g_V);
    cudaGetSymbolAddress((void**)&bf.Sc,  g_Sc);
    cudaGetSymbolAddress((void**)&bf.Ctx, g_Ctx);
    cudaGetSymbolAddress((void**)&bf.Tmp, g_Tmp);
    cudaGetSymbolAddress((void**)&bf.Ffn, g_Ffn);
    cudaGetSymbolAddress((void**)&bf.Enc, g_Enc);
    cudaGetSymbolAddress((void**)&bf.Dec, g_Dec);

    const size_t WP = (size_t)Dm * Dm;       // per-layer projection weight size
    const size_t W1S = (size_t)Dm * FF;
    const size_t W2S = (size_t)FF * Dm;

    // ---- encoder stack ----
    const float* src = enc_in;
    for (int i = 0; i < NL; i++) {
        attn_block(src, src, enc_Wq + i * WP, enc_Wk + i * WP, enc_Wv + i * WP,
                   enc_Wo + i * WP, nullptr, bf.Enc, bf);
        ffn_block(bf.Enc, enc_W1 + i * W1S, enc_W2 + i * W2S, bf.Enc, bf);
        src = bf.Enc;
    }

    // ---- decoder stack ----
    const float* dsrc = dec_in;
    for (int i = 0; i < NL; i++) {
        attn_block(dsrc, dsrc, sa_Wq + i * WP, sa_Wk + i * WP, sa_Wv + i * WP,
                   sa_Wo + i * WP, mask, bf.Dec, bf);
        attn_block(bf.Dec, bf.Enc, ca_Wq + i * WP, ca_Wk + i * WP, ca_Wv + i * WP,
                   ca_Wo + i * WP, nullptr, bf.Dec, bf);
        float* out = (i == NL - 1) ? (float*)d_out : bf.Dec;
        ffn_block(bf.Dec, dec_W1 + i * W1S, dec_W2 + i * W2S, out, bf);
        dsrc = bf.Dec;
    }
}

// round 3
// speedup vs baseline: 1.7999x; 1.7999x over previous
#include <cuda_runtime.h>
#include <cstdint>

#define Dm 512
#define Sq 512
#define Bz 4
#define Hh 8
#define FF 2048
#define NL 6
#define TOK (Bz*Sq)        // 2048 tokens
#define NEGV (-1000000000.0f)

// ---------------- scratch (no allocations allowed) ----------------
__device__ float g_Q  [TOK*Dm];
__device__ float g_K  [TOK*Dm];
__device__ float g_V  [TOK*Dm];
__device__ float g_Sc [Bz*Hh*Sq*Sq];   // 32 MB attention scores
__device__ float g_Ctx[TOK*Dm];
__device__ float g_Tmp[TOK*Dm];
__device__ float g_Ffn[TOK*FF];
__device__ float g_Enc[TOK*Dm];
__device__ float g_Dec[TOK*Dm];

// ---------------- PTX helpers ----------------
__device__ __forceinline__ uint32_t smem_u32(const void* p) {
    return (uint32_t)__cvta_generic_to_shared(p);
}
__device__ __forceinline__ void cpasync16(uint32_t dst, const void* src) {
    asm volatile("cp.async.cg.shared.global [%0], [%1], 16;\n" :: "r"(dst), "l"(src));
}
__device__ __forceinline__ void cp_commit() { asm volatile("cp.async.commit_group;\n"); }
template<int N> __device__ __forceinline__ void cp_wait() {
    asm volatile("cp.async.wait_group %0;\n" :: "n"(N));
}
// D += A(16x8) * B(8x8), tf32 inputs, fp32 accum
__device__ __forceinline__ void mma8(float* c, const uint32_t* a, const uint32_t* b) {
    asm volatile("mma.sync.aligned.m16n8k8.row.col.f32.tf32.tf32.f32 "
                 "{%0,%1,%2,%3},{%4,%5,%6,%7},{%8,%9},{%0,%1,%2,%3};\n"
                 : "+f"(c[0]), "+f"(c[1]), "+f"(c[2]), "+f"(c[3])
                 : "r"(a[0]), "r"(a[1]), "r"(a[2]), "r"(a[3]), "r"(b[0]), "r"(b[1]));
}
// 3xTF32 split: x = hi + lo (both tf32-representable, rna-rounded)
__device__ __forceinline__ void split_tf32(float x, uint32_t& hi, uint32_t& lo) {
    uint32_t h;
    asm("cvt.rna.tf32.f32 %0, %1;\n" : "=r"(h) : "f"(x));
    float r = x - __uint_as_float(h);
    uint32_t l;
    asm("cvt.rna.tf32.f32 %0, %1;\n" : "=r"(l) : "f"(r));
    hi = h; lo = l;
}
// C += A*B with 3 mmas: hi*hi + lo*hi + hi*lo
__device__ __forceinline__ void mma3(float* c, const uint32_t* ah, const uint32_t* al,
                                     const uint32_t* bh, const uint32_t* bl) {
    mma8(c, al, bh);
    mma8(c, ah, bl);
    mma8(c, ah, bh);
}

// ================= main GEMM: C[M,N] = A[M,K] @ B[K,N] =================
// 128x64 block, BK=16, 4 warps (warp tile 64x32), cp.async double-buffered.
#define BM 128
#define BN 64
#define BK 16
#define ASTR 20   // (BK+4); 20 % 8 == 4  -> conflict-free A frags
#define BSTR 72   // (BN+8); 72 % 32 == 8 -> conflict-free B frags
template<bool RELU>
__global__ __launch_bounds__(128) void gemm_tf32(
    const float* __restrict__ A, const float* __restrict__ B,
    float* __restrict__ C, int M, int N, int K) {
    __shared__ float As[2][BM * ASTR];
    __shared__ float Bs[2][BK * BSTR];
    const int t = threadIdx.x;
    const int warp = t >> 5, lane = t & 31, g = lane >> 2, tg = lane & 3;
    const int wm = (warp & 1) * 64, wn = (warp >> 1) * 32;
    const int rowBase = blockIdx.y * BM, colBase = blockIdx.x * BN;
    const int am = t >> 2, ak = (t & 3) * 4;
    const int bk = t >> 4, bn = (t & 15) * 4;

    float c[4][4][4] = {};

    auto copy_tiles = [&](int buf, int k0) {
        #pragma unroll
        for (int i = 0; i < 4; i++) {
            int m = am + i * 32;
            cpasync16(smem_u32(&As[buf][m * ASTR + ak]),
                      &A[(size_t)(rowBase + m) * K + k0 + ak]);
        }
        #pragma unroll
        for (int i = 0; i < 2; i++) {
            int k = bk + i * 8;
            cpasync16(smem_u32(&Bs[buf][k * BSTR + bn]),
                      &B[(size_t)(k0 + k) * N + colBase + bn]);
        }
        cp_commit();
    };

    const int iters = K / BK;
    copy_tiles(0, 0);
    for (int i = 0; i < iters; i++) {
        const int cur = i & 1;
        if (i + 1 < iters) { copy_tiles(cur ^ 1, (i + 1) * BK); cp_wait<1>(); }
        else               { cp_wait<0>(); }
        __syncthreads();
        #pragma unroll
        for (int kk = 0; kk < BK; kk += 8) {
            uint32_t ah[4][4], al[4][4], bh[4][2], bl[4][2];
            #pragma unroll
            for (int mt = 0; mt < 4; mt++) {
                const float* base = &As[cur][(wm + mt * 16) * ASTR + kk];
                split_tf32(base[g * ASTR + tg],           ah[mt][0], al[mt][0]);
                split_tf32(base[(g + 8) * ASTR + tg],     ah[mt][1], al[mt][1]);
                split_tf32(base[g * ASTR + tg + 4],       ah[mt][2], al[mt][2]);
                split_tf32(base[(g + 8) * ASTR + tg + 4], ah[mt][3], al[mt][3]);
            }
            #pragma unroll
            for (int nt = 0; nt < 4; nt++) {
                const float* base = &Bs[cur][kk * BSTR + wn + nt * 8 + g];
                split_tf32(base[tg * BSTR],       bh[nt][0], bl[nt][0]);
                split_tf32(base[(tg + 4) * BSTR], bh[nt][1], bl[nt][1]);
            }
            #pragma unroll
            for (int mt = 0; mt < 4; mt++)
                #pragma unroll
                for (int nt = 0; nt < 4; nt++)
                    mma3(c[mt][nt], ah[mt], al[mt], bh[nt], bl[nt]);
        }
        __syncthreads();
    }
    // epilogue
    #pragma unroll
    for (int mt = 0; mt < 4; mt++) {
        #pragma unroll
        for (int nt = 0; nt < 4; nt++) {
            int r0 = rowBase + wm + mt * 16 + g;
            int col = colBase + wn + nt * 8 + tg * 2;
            float2 v0 = {c[mt][nt][0], c[mt][nt][1]};
            float2 v1 = {c[mt][nt][2], c[mt][nt][3]};
            if (RELU) {
                v0.x = fmaxf(v0.x, 0.f); v0.y = fmaxf(v0.y, 0.f);
                v1.x = fmaxf(v1.x, 0.f); v1.y = fmaxf(v1.y, 0.f);
            }
            *(float2*)&C[(size_t)r0 * N + col] = v0;
            *(float2*)&C[(size_t)(r0 + 8) * N + col] = v1;
        }
    }
}

// ============ scores[bh,q,c] = (Q[b,q,h,:] . K[b,c,h,:]) / 8 ============
#define QSTR 68
__global__ __launch_bounds__(128) void scores_tf32(
    const float* __restrict__ Q, const float* __restrict__ Kx, float* __restrict__ S) {
    __shared__ float Qs[64 * QSTR];
    __shared__ float Ks[64 * QSTR];
    const int bh = blockIdx.z, b = bh >> 3, h = bh & 7;
    const int q0 = blockIdx.y * 64, c0 = blockIdx.x * 64;
    const int t = threadIdx.x;
    const int warp = t >> 5, lane = t & 31, g = lane >> 2, tg = lane & 3;
    const int wm = (warp & 1) * 32, wn = (warp >> 1) * 32;
    const int lr = t >> 4, ld4 = (t & 15) * 4;

    #pragma unroll
    for (int i = 0; i < 8; i++) {
        int r = lr + i * 8;
        cpasync16(smem_u32(&Qs[r * QSTR + ld4]),
                  &Q[(size_t)((b * Sq + q0 + r) * Dm) + h * 64 + ld4]);
        cpasync16(smem_u32(&Ks[r * QSTR + ld4]),
                  &Kx[(size_t)((b * Sq + c0 + r) * Dm) + h * 64 + ld4]);
    }
    cp_commit(); cp_wait<0>();
    __syncthreads();

    float c[2][4][4] = {};
    #pragma unroll
    for (int kk = 0; kk < 64; kk += 8) {
        uint32_t ah[2][4], al[2][4], bh[4][2], bl[4][2];
        #pragma unroll
        for (int mt = 0; mt < 2; mt++) {
            const float* base = &Qs[(wm + mt * 16) * QSTR + kk];
            split_tf32(base[g * QSTR + tg],           ah[mt][0], al[mt][0]);
            split_tf32(base[(g + 8) * QSTR + tg],     ah[mt][1], al[mt][1]);
            split_tf32(base[g * QSTR + tg + 4],       ah[mt][2], al[mt][2]);
            split_tf32(base[(g + 8) * QSTR + tg + 4], ah[mt][3], al[mt][3]);
        }
        #pragma unroll
        for (int nt = 0; nt < 4; nt++) {
            const float* base = &Ks[(wn + nt * 8 + g) * QSTR + kk];
            split_tf32(base[tg],     bh[nt][0], bl[nt][0]);
            split_tf32(base[tg + 4], bh[nt][1], bl[nt][1]);
        }
        #pragma unroll
        for (int mt = 0; mt < 2; mt++)
            #pragma unroll
            for (int nt = 0; nt < 4; nt++)
                mma3(c[mt][nt], ah[mt], al[mt], bh[nt], bl[nt]);
    }
    #pragma unroll
    for (int mt = 0; mt < 2; mt++)
        #pragma unroll
        for (int nt = 0; nt < 4; nt++) {
            int r0 = q0 + wm + mt * 16 + g;
            int col = c0 + wn + nt * 8 + tg * 2;
            float2 v0 = {c[mt][nt][0] * 0.125f, c[mt][nt][1] * 0.125f};
            float2 v1 = {c[mt][nt][2] * 0.125f, c[mt][nt][3] * 0.125f};
            *(float2*)&S[(size_t)(bh * Sq + r0) * Sq + col] = v0;
            *(float2*)&S[(size_t)(bh * Sq + r0 + 8) * Sq + col] = v1;
        }
}

// ============ ctx[b,q,h,:] = P[bh] @ V[b,:,h,:]  (512x64, K=512) ============
#define PSTR 68
#define VSTR 72
__global__ __launch_bounds__(128) void ctx_tf32(
    const float* __restrict__ P, const float* __restrict__ V, float* __restrict__ C) {
    __shared__ float Ps[64 * PSTR];
    __shared__ float Vs[64 * VSTR];
    const int bh = blockIdx.y, b = bh >> 3, h = bh & 7;
    const int q0 = blockIdx.x * 64;
    const int t = threadIdx.x;
    const int warp = t >> 5, lane = t & 31, g = lane >> 2, tg = lane & 3;
    const int wm = (warp & 1) * 32, wn = (warp >> 1) * 32;
    const int lr = t >> 4, ld4 = (t & 15) * 4;

    float c[2][4][4] = {};
    for (int k0 = 0; k0 < Sq; k0 += 64) {
        #pragma unroll
        for (int i = 0; i < 8; i++) {
            int r = lr + i * 8;
            cpasync16(smem_u32(&Ps[r * PSTR + ld4]),
                      &P[(size_t)(bh * Sq + q0 + r) * Sq + k0 + ld4]);
            cpasync16(smem_u32(&Vs[r * VSTR + ld4]),
                      &V[(size_t)((b * Sq + k0 + r) * Dm) + h * 64 + ld4]);
        }
        cp_commit(); cp_wait<0>();
        __syncthreads();
        #pragma unroll
        for (int kk = 0; kk < 64; kk += 8) {
            uint32_t ah[2][4], al[2][4], bh[4][2], bl[4][2];
            #pragma unroll
            for (int mt = 0; mt < 2; mt++) {
                const float* base = &Ps[(wm + mt * 16) * PSTR + kk];
                split_tf32(base[g * PSTR + tg],           ah[mt][0], al[mt][0]);
                split_tf32(base[(g + 8) * PSTR + tg],     ah[mt][1], al[mt][1]);
                split_tf32(base[g * PSTR + tg + 4],       ah[mt][2], al[mt][2]);
                split_tf32(base[(g + 8) * PSTR + tg + 4], ah[mt][3], al[mt][3]);
            }
            #pragma unroll
            for (int nt = 0; nt < 4; nt++) {
                const float* base = &Vs[kk * VSTR + wn + nt * 8 + g];
                split_tf32(base[tg * VSTR],       bh[nt][0], bl[nt][0]);
                split_tf32(base[(tg + 4) * VSTR], bh[nt][1], bl[nt][1]);
            }
            #pragma unroll
            for (int mt = 0; mt < 2; mt++)
                #pragma unroll
                for (int nt = 0; nt < 4; nt++)
                    mma3(c[mt][nt], ah[mt], al[mt], bh[nt], bl[nt]);
        }
        __syncthreads();
    }
    #pragma unroll
    for (int mt = 0; mt < 2; mt++)
        #pragma unroll
        for (int nt = 0; nt < 4; nt++) {
            int r0 = q0 + wm + mt * 16 + g;
            int col = h * 64 + wn + nt * 8 + tg * 2;
            *(float2*)&C[(size_t)((b * Sq + r0) * Dm) + col] =
                make_float2(c[mt][nt][0], c[mt][nt][1]);
            *(float2*)&C[(size_t)((b * Sq + r0 + 8) * Dm) + col] =
                make_float2(c[mt][nt][2], c[mt][nt][3]);
        }
}

// ---------------- row softmax over 512, optional mask ----------------
__global__ void softmax_kernel(float* __restrict__ S, const int* __restrict__ mask) {
    const int row = blockIdx.x;
    const int q = row & 511;
    const int bh = row >> 9;
    const int b = bh >> 3;
    float* p = S + (size_t)row * Sq;
    const int t = threadIdx.x;
    float v0 = p[t], v1 = p[t + 256];
    if (mask) {
        const int* mrow = mask + (size_t)(b * Sq + q) * Sq;
        if (mrow[t] == 0)       v0 = NEGV;
        if (mrow[t + 256] == 0) v1 = NEGV;
    }
    __shared__ float red[256];
    red[t] = fmaxf(v0, v1); __syncthreads();
    for (int s = 128; s > 0; s >>= 1) { if (t < s) red[t] = fmaxf(red[t], red[t + s]); __syncthreads(); }
    float m = red[0]; __syncthreads();
    float e0 = __expf(v0 - m), e1 = __expf(v1 - m);
    red[t] = e0 + e1; __syncthreads();
    for (int s = 128; s > 0; s >>= 1) { if (t < s) red[t] += red[t + s]; __syncthreads(); }
    float inv = 1.0f / red[0];
    p[t] = e0 * inv; p[t + 256] = e1 * inv;
}

// ---------------- out = LayerNorm(X + R) ----------------
__global__ void add_ln_kernel(const float* __restrict__ X, const float* __restrict__ R,
                              float* __restrict__ O) {
    const int row = blockIdx.x;
    const int t = threadIdx.x;
    const float* x = X + (size_t)row * Dm;
    const float* r = R + (size_t)row * Dm;
    float v0 = x[t] + r[t], v1 = x[t + 256] + r[t + 256];
    __shared__ float red[256];
    red[t] = v0 + v1; __syncthreads();
    for (int s = 128; s > 0; s >>= 1) { if (t < s) red[t] += red[t + s]; __syncthreads(); }
    float mean = red[0] * (1.0f / Dm); __syncthreads();
    float d0 = v0 - mean, d1 = v1 - mean;
    red[t] = d0 * d0 + d1 * d1; __syncthreads();
    for (int s = 128; s > 0; s >>= 1) { if (t < s) red[t] += red[t + s]; __syncthreads(); }
    float inv = rsqrtf(red[0] * (1.0f / Dm) + 1e-5f);
    float* o = O + (size_t)row * Dm;
    o[t] = d0 * inv; o[t + 256] = d1 * inv;
}

// ---------------- host orchestration ----------------
struct Bufs { float *Q, *K, *V, *Sc, *Ctx, *Tmp, *Ffn, *Enc, *Dec; };

static void attn_block(const float* xq, const float* xkv,
                       const float* Wq, const float* Wk, const float* Wv, const float* Wo,
                       const int* mask, float* dst, const Bufs& bf) {
    dim3 gP(Dm / BN, TOK / BM);
    gemm_tf32<false><<<gP, 128>>>(xq,  Wq, bf.Q, TOK, Dm, Dm);
    gemm_tf32<false><<<gP, 128>>>(xkv, Wk, bf.K, TOK, Dm, Dm);
    gemm_tf32<false><<<gP, 128>>>(xkv, Wv, bf.V, TOK, Dm, Dm);
    scores_tf32<<<dim3(Sq / 64, Sq / 64, Bz * Hh), 128>>>(bf.Q, bf.K, bf.Sc);
    softmax_kernel<<<Bz * Hh * Sq, 256>>>(bf.Sc, mask);
    ctx_tf32<<<dim3(Sq / 64, Bz * Hh), 128>>>(bf.Sc, bf.V, bf.Ctx);
    gemm_tf32<false><<<gP, 128>>>(bf.Ctx, Wo, bf.Tmp, TOK, Dm, Dm);
    add_ln_kernel<<<TOK, 256>>>(bf.Tmp, xq, dst);
}

static void ffn_block(const float* x, const float* W1, const float* W2,
                      float* dst, const Bufs& bf) {
    gemm_tf32<true ><<<dim3(FF / BN, TOK / BM), 128>>>(x, W1, bf.Ffn, TOK, FF, Dm);
    gemm_tf32<false><<<dim3(Dm / BN, TOK / BM), 128>>>(bf.Ffn, W2, bf.Tmp, TOK, Dm, FF);
    add_ln_kernel<<<TOK, 256>>>(bf.Tmp, x, dst);
}

extern "C" void kernel_launch(void* const* d_in, const int* in_sizes, int n_in,
                              void* d_out, int out_size) {
    const float* enc_in  = (const float*)d_in[0];
    const float* dec_in  = (const float*)d_in[1];
    const int*   mask    = (const int*)  d_in[2];
    const float* enc_Wq  = (const float*)d_in[3];
    const float* enc_Wk  = (const float*)d_in[4];
    const float* enc_Wv  = (const float*)d_in[5];
    const float* enc_Wo  = (const float*)d_in[6];
    const float* enc_W1  = (const float*)d_in[7];
    const float* enc_W2  = (const float*)d_in[8];
    const float* sa_Wq   = (const float*)d_in[9];
    const float* sa_Wk   = (const float*)d_in[10];
    const float* sa_Wv   = (const float*)d_in[11];
    const float* sa_Wo   = (const float*)d_in[12];
    const float* ca_Wq   = (const float*)d_in[13];
    const float* ca_Wk   = (const float*)d_in[14];
    const float* ca_Wv   = (const float*)d_in[15];
    const float* ca_Wo   = (const float*)d_in[16];
    const float* dec_W1  = (const float*)d_in[17];
    const float* dec_W2  = (const float*)d_in[18];

    Bufs bf;
    cudaGetSymbolAddress((void**)&bf.Q,   g_Q);
    cudaGetSymbolAddress((void**)&bf.K,   g_K);
    cudaGetSymbolAddress((void**)&bf.V,   g_V);
    cudaGetSymbolAddress((void**)&bf.Sc,  g_Sc);
    cudaGetSymbolAddress((void**)&bf.Ctx, g_Ctx);
    cudaGetSymbolAddress((void**)&bf.Tmp, g_Tmp);
    cudaGetSymbolAddress((void**)&bf.Ffn, g_Ffn);
    cudaGetSymbolAddress((void**)&bf.Enc, g_Enc);
    cudaGetSymbolAddress((void**)&bf.Dec, g_Dec);

    const size_t WP  = (size_t)Dm * Dm;
    const size_t W1S = (size_t)Dm * FF;
    const size_t W2S = (size_t)FF * Dm;

    // ---- encoder stack ----
    const float* src = enc_in;
    for (int i = 0; i < NL; i++) {
        attn_block(src, src, enc_Wq + i * WP, enc_Wk + i * WP, enc_Wv + i * WP,
                   enc_Wo + i * WP, nullptr, bf.Enc, bf);
        ffn_block(bf.Enc, enc_W1 + i * W1S, enc_W2 + i * W2S, bf.Enc, bf);
        src = bf.Enc;
    }

    // ---- decoder stack ----
    const float* dsrc = dec_in;
    for (int i = 0; i < NL; i++) {
        attn_block(dsrc, dsrc, sa_Wq + i * WP, sa_Wk + i * WP, sa_Wv + i * WP,
                   sa_Wo + i * WP, mask, bf.Dec, bf);
        attn_block(bf.Dec, bf.Enc, ca_Wq + i * WP, ca_Wk + i * WP, ca_Wv + i * WP,
                   ca_Wo + i * WP, nullptr, bf.Dec, bf);
        float* out = (i == NL - 1) ? (float*)d_out : bf.Dec;
        ffn_block(bf.Dec, dec_W1 + i * W1S, dec_W2 + i * W2S, out, bf);
        dsrc = bf.Dec;
    }
}